// round 12
// baseline (speedup 1.0000x reference)
#include <cuda_runtime.h>
#include <cuda_bf16.h>
#include <cuda_fp16.h>
#include <cstdint>

#define NN    100000
#define EE    1600000
#define INC   256
#define OUTC  128

// ------------------------- device scratch -------------------------
__device__ float  g_Hf[(size_t)NN * OUTC];    // H = X @ W^T (fp32)
__device__ int    g_row_ptr[NN + 1];
__device__ __half g_Wh[OUTC * INC];           // W in fp16

// ------------------------- helpers -------------------------
__device__ __forceinline__ uint32_t smem_u32(const void* p) {
    uint32_t a;
    asm("{ .reg .u64 t; cvta.to.shared.u64 t, %1; cvt.u32.u64 %0, t; }"
        : "=r"(a) : "l"(p));
    return a;
}
__device__ __forceinline__ void ldm_x4(uint32_t* r, uint32_t addr) {
    asm volatile("ldmatrix.sync.aligned.m8n8.x4.shared.b16 {%0,%1,%2,%3}, [%4];"
                 : "=r"(r[0]), "=r"(r[1]), "=r"(r[2]), "=r"(r[3]) : "r"(addr));
}
__device__ __forceinline__ void mma_fp16(float* c, const uint32_t* a, const uint32_t* b) {
    asm volatile(
        "mma.sync.aligned.m16n8k16.row.col.f32.f16.f16.f32 "
        "{%0,%1,%2,%3}, {%4,%5,%6,%7}, {%8,%9}, {%0,%1,%2,%3};"
        : "+f"(c[0]), "+f"(c[1]), "+f"(c[2]), "+f"(c[3])
        : "r"(a[0]), "r"(a[1]), "r"(a[2]), "r"(a[3]), "r"(b[0]), "r"(b[1]));
}

// ------------------------- Kernel 0: W -> fp16 -------------------------
__global__ void wconv_kernel(const float* __restrict__ W) {
    int i = blockIdx.x * blockDim.x + threadIdx.x;
    if (i < OUTC * INC)
        g_Wh[i] = __float2half_rn(W[i]);
}

// ------------------------- Kernel 1: fp16 mma.sync GEMM -------------------------
// H[m][n] = sum_k X[m][k] * W[n][k].  CTA tile 128x128, K-tiles of 64.
// 8 warps: warp_m = wid%4 (32 rows), warp_n = wid/4 (64 cols).
// SMEM (halves, row stride LDH=72 for conflict-free ldmatrix): A[128][72], B[128][72]
#define LDH 72
#define SM_A 0
#define SM_B (128 * LDH)
#define SM_HALVES (2 * 128 * LDH)
#define SM_BYTES (SM_HALVES * 2)   // 36864

__global__ __launch_bounds__(256, 2)
void gemm_tc_kernel(const float* __restrict__ X)
{
    extern __shared__ __half sm[];
    const uint32_t sb = smem_u32(sm);

    const int tid = threadIdx.x;
    const int wid = tid >> 5;
    const int lane = tid & 31;
    const int block_row = blockIdx.x * 128;

    const int wm = (wid & 3) * 32;   // warp row offset
    const int wn = (wid >> 2) * 64;  // warp col offset

    float c[2][8][4];
#pragma unroll
    for (int mi = 0; mi < 2; mi++)
#pragma unroll
        for (int ni = 0; ni < 8; ni++)
#pragma unroll
            for (int j = 0; j < 4; j++)
                c[mi][ni][j] = 0.0f;

    const int a_row = (lane & 7) + 8 * ((lane >> 3) & 1);
    const int a_kh  = 8 * (lane >> 4);
    // B ldmatrix.x4 lane mapping for an ni-PAIR (16 n-rows x 2 k-halves)
    const int b_row = (lane & 7) + 8 * (lane >> 4);
    const int b_kh  = 8 * ((lane >> 3) & 1);

#pragma unroll 1
    for (int kt = 0; kt < 4; kt++) {
        const int k0 = kt * 64;
        if (kt) __syncthreads();

        // --- X tile: 128 rows x 64 floats -> fp16 ---
#pragma unroll
        for (int i = 0; i < 8; i++) {
            int slot = i * 256 + tid;          // 0..2047 float4 slots
            int row  = slot >> 4;
            int kq   = (slot & 15) << 2;
            int gm   = block_row + row;
            float4 v = make_float4(0.f, 0.f, 0.f, 0.f);
            if (gm < NN)
                v = *reinterpret_cast<const float4*>(X + (size_t)gm * INC + k0 + kq);
            __half2 p0 = __floats2half2_rn(v.x, v.y);
            __half2 p1 = __floats2half2_rn(v.z, v.w);
            uint2 w;
            w.x = *reinterpret_cast<uint32_t*>(&p0);
            w.y = *reinterpret_cast<uint32_t*>(&p1);
            *reinterpret_cast<uint2*>(&sm[SM_A + row * LDH + kq]) = w;
        }
        // --- W tile: 128 n x 64 halves (1024 uint4 slots, 8 halves each) ---
#pragma unroll
        for (int i = 0; i < 4; i++) {
            int slot = i * 256 + tid;          // 0..1023
            int n    = slot >> 3;
            int kc   = (slot & 7) << 3;
            *reinterpret_cast<uint4*>(&sm[SM_B + n * LDH + kc]) =
                *reinterpret_cast<const uint4*>(g_Wh + n * INC + k0 + kc);
        }
        __syncthreads();

        // --- compute: 4 k16 steps ---
#pragma unroll
        for (int ks = 0; ks < 4; ks++) {
            uint32_t a[2][4];
#pragma unroll
            for (int mi = 0; mi < 2; mi++) {
                int hoff = (wm + mi * 16 + a_row) * LDH + ks * 16 + a_kh;
                ldm_x4(a[mi], sb + 2 * (SM_A + hoff));
            }
#pragma unroll
            for (int p = 0; p < 4; p++) {      // ni pairs (2p, 2p+1)
                uint32_t bq[4];
                int hoff = (wn + p * 16 + b_row) * LDH + ks * 16 + b_kh;
                ldm_x4(bq, sb + 2 * (SM_B + hoff));
#pragma unroll
                for (int mi = 0; mi < 2; mi++) {
                    mma_fp16(c[mi][2 * p + 0], a[mi], bq + 0);
                    mma_fp16(c[mi][2 * p + 1], a[mi], bq + 2);
                }
            }
        }
    }

    // --- epilogue: write fp32 H (float2 per fragment half) ---
    const int r0 = (lane >> 2);
    const int cb = (lane & 3) * 2;
#pragma unroll
    for (int mi = 0; mi < 2; mi++) {
#pragma unroll
        for (int ni = 0; ni < 8; ni++) {
            int col = wn + ni * 8 + cb;
            int gm0 = block_row + wm + mi * 16 + r0;
            int gm1 = gm0 + 8;
            if (gm0 < NN)
                *reinterpret_cast<float2*>(g_Hf + (size_t)gm0 * OUTC + col) =
                    make_float2(c[mi][ni][0], c[mi][ni][1]);
            if (gm1 < NN)
                *reinterpret_cast<float2*>(g_Hf + (size_t)gm1 * OUTC + col) =
                    make_float2(c[mi][ni][2], c[mi][ni][3]);
        }
    }
}

// ------------------------- Kernel 2: CSR row pointers (A_rows sorted) -------------------------
__global__ void row_ptr_kernel(const int* __restrict__ A_rows)
{
    int r = blockIdx.x * blockDim.x + threadIdx.x;
    if (r > NN) return;
    int lo = 0, hi = EE;
    while (lo < hi) {
        int mid = (lo + hi) >> 1;
        if (A_rows[mid] < r) lo = mid + 1;
        else                 hi = mid;
    }
    g_row_ptr[r] = lo;
}

// ------------------------- Kernel 3: CSR SpMM, warp per row, fp32 H -----------------
// Lane owns 4 channels (float4 = 16B). Metadata via shuffles. No conversions.
// Per edge: 2 shfl + addr + 1 LDG.128 (512B coalesced) + 4 FFMA.
__global__ __launch_bounds__(256)
void spmm_kernel(const int*   __restrict__ A_cols,
                 const float* __restrict__ A_vals,
                 float*       __restrict__ out)
{
    const int lane = threadIdx.x & 31;
    const int r    = blockIdx.x * 8 + (threadIdx.x >> 5);
    if (r >= NN) return;                       // warp-uniform

    const int beg = g_row_ptr[r];
    const int end = g_row_ptr[r + 1];

    float4 acc = make_float4(0.f, 0.f, 0.f, 0.f);
    const float* __restrict__ lanep = g_Hf + lane * 4;

#pragma unroll 1
    for (int base = beg; base < end; base += 32) {
        int   e   = base + lane;
        int   col = 0;
        float v   = 0.f;
        if (e < end) { col = __ldg(A_cols + e); v = __ldg(A_vals + e); }
        const int cnt = min(32, end - base);

#pragma unroll 4
        for (int j = 0; j < cnt; j++) {
            int   cj = __shfl_sync(0xffffffffu, col, j);
            float vj = __shfl_sync(0xffffffffu, v,   j);
            float4 h = *reinterpret_cast<const float4*>(lanep + ((size_t)cj << 7));
            acc.x = fmaf(vj, h.x, acc.x);
            acc.y = fmaf(vj, h.y, acc.y);
            acc.z = fmaf(vj, h.z, acc.z);
            acc.w = fmaf(vj, h.w, acc.w);
        }
    }

    *reinterpret_cast<float4*>(out + (size_t)r * OUTC + lane * 4) = acc;
}

// ---------------------------------------------------------------------------
extern "C" void kernel_launch(void* const* d_in, const int* in_sizes, int n_in,
                              void* d_out, int out_size)
{
    const float* X      = (const float*)d_in[0];   // [NN, INC]
    const float* W      = (const float*)d_in[1];   // [OUTC, INC]
    const int*   A_rows = (const int*)  d_in[2];   // [EE] sorted
    const int*   A_cols = (const int*)  d_in[3];   // [EE]
    const float* A_vals = (const float*)d_in[4];   // [EE]
    float*       out    = (float*)d_out;           // [NN, OUTC]

    cudaFuncSetAttribute(gemm_tc_kernel,
                         cudaFuncAttributeMaxDynamicSharedMemorySize, SM_BYTES);

    wconv_kernel<<<(OUTC * INC + 255) / 256, 256>>>(W);
    gemm_tc_kernel<<<(NN + 127) / 128, 256, SM_BYTES>>>(X);
    row_ptr_kernel<<<(NN + 1 + 255) / 256, 256>>>(A_rows);
    spmm_kernel<<<(NN + 7) / 8, 256>>>(A_cols, A_vals, out);
}

// round 14
// speedup vs baseline: 1.1132x; 1.1132x over previous
#include <cuda_runtime.h>
#include <cuda_bf16.h>
#include <cuda_fp16.h>
#include <cstdint>

#define NN    100000
#define EE    1600000
#define INC   256
#define OUTC  128

// ------------------------- device scratch -------------------------
__device__ __half g_Hh[(size_t)NN * OUTC];    // H = X @ W^T (fp16)
__device__ int    g_row_ptr[NN + 1];
__device__ __half g_Wh[OUTC * INC];           // W in fp16

// ------------------------- helpers -------------------------
__device__ __forceinline__ uint32_t smem_u32(const void* p) {
    uint32_t a;
    asm("{ .reg .u64 t; cvta.to.shared.u64 t, %1; cvt.u32.u64 %0, t; }"
        : "=r"(a) : "l"(p));
    return a;
}
__device__ __forceinline__ void ldm_x4(uint32_t* r, uint32_t addr) {
    asm volatile("ldmatrix.sync.aligned.m8n8.x4.shared.b16 {%0,%1,%2,%3}, [%4];"
                 : "=r"(r[0]), "=r"(r[1]), "=r"(r[2]), "=r"(r[3]) : "r"(addr));
}
__device__ __forceinline__ void mma_fp16(float* c, const uint32_t* a, const uint32_t* b) {
    asm volatile(
        "mma.sync.aligned.m16n8k16.row.col.f32.f16.f16.f32 "
        "{%0,%1,%2,%3}, {%4,%5,%6,%7}, {%8,%9}, {%0,%1,%2,%3};"
        : "+f"(c[0]), "+f"(c[1]), "+f"(c[2]), "+f"(c[3])
        : "r"(a[0]), "r"(a[1]), "r"(a[2]), "r"(a[3]), "r"(b[0]), "r"(b[1]));
}

// ------------------------- Kernel 0: W -> fp16 -------------------------
__global__ void wconv_kernel(const float* __restrict__ W) {
    int i = blockIdx.x * blockDim.x + threadIdx.x;
    if (i < OUTC * INC)
        g_Wh[i] = __float2half_rn(W[i]);
}

// ------------------------- Kernel 1: fp16 mma.sync GEMM, 512 threads ----------------
// CTA tile 128x128, K-tiles of 64. 16 warps in 4x4: warp tile 32 rows x 32 cols.
// SMEM (halves, row stride LDH=72): A[128][72], B[128][72]
#define LDH 72
#define SM_A 0
#define SM_B (128 * LDH)
#define SM_HALVES (2 * 128 * LDH)
#define SM_BYTES (SM_HALVES * 2)   // 36864

__global__ __launch_bounds__(512, 2)
void gemm_tc_kernel(const float* __restrict__ X)
{
    extern __shared__ __half sm[];
    const uint32_t sb = smem_u32(sm);

    const int tid = threadIdx.x;          // 0..511
    const int wid = tid >> 5;             // 0..15
    const int lane = tid & 31;
    const int block_row = blockIdx.x * 128;

    const int wm = (wid & 3) * 32;        // warp row offset
    const int wn = (wid >> 2) * 32;       // warp col offset

    float c[2][4][4];
#pragma unroll
    for (int mi = 0; mi < 2; mi++)
#pragma unroll
        for (int ni = 0; ni < 4; ni++)
#pragma unroll
            for (int j = 0; j < 4; j++)
                c[mi][ni][j] = 0.0f;

    const int a_row = (lane & 7) + 8 * ((lane >> 3) & 1);
    const int a_kh  = 8 * (lane >> 4);
    // B ldmatrix.x4 lane mapping for an ni-PAIR (16 n-rows x 2 k-halves)
    const int b_row = (lane & 7) + 8 * (lane >> 4);
    const int b_kh  = 8 * ((lane >> 3) & 1);

#pragma unroll 1
    for (int kt = 0; kt < 4; kt++) {
        const int k0 = kt * 64;
        if (kt) __syncthreads();

        // --- X tile: 128 rows x 64 floats -> fp16 (2048 float4 slots, 4/thread) ---
#pragma unroll
        for (int i = 0; i < 4; i++) {
            int slot = i * 512 + tid;
            int row  = slot >> 4;
            int kq   = (slot & 15) << 2;
            int gm   = block_row + row;
            float4 v = make_float4(0.f, 0.f, 0.f, 0.f);
            if (gm < NN)
                v = *reinterpret_cast<const float4*>(X + (size_t)gm * INC + k0 + kq);
            __half2 p0 = __floats2half2_rn(v.x, v.y);
            __half2 p1 = __floats2half2_rn(v.z, v.w);
            uint2 w;
            w.x = *reinterpret_cast<uint32_t*>(&p0);
            w.y = *reinterpret_cast<uint32_t*>(&p1);
            *reinterpret_cast<uint2*>(&sm[SM_A + row * LDH + kq]) = w;
        }
        // --- W tile: 128 n x 64 halves (1024 uint4 slots, 2/thread) ---
#pragma unroll
        for (int i = 0; i < 2; i++) {
            int slot = i * 512 + tid;
            int n    = slot >> 3;
            int kc   = (slot & 7) << 3;
            *reinterpret_cast<uint4*>(&sm[SM_B + n * LDH + kc]) =
                *reinterpret_cast<const uint4*>(g_Wh + n * INC + k0 + kc);
        }
        __syncthreads();

        // --- compute: 4 k16 steps, warp tile 32x32 ---
#pragma unroll
        for (int ks = 0; ks < 4; ks++) {
            uint32_t a[2][4];
#pragma unroll
            for (int mi = 0; mi < 2; mi++) {
                int hoff = (wm + mi * 16 + a_row) * LDH + ks * 16 + a_kh;
                ldm_x4(a[mi], sb + 2 * (SM_A + hoff));
            }
#pragma unroll
            for (int p = 0; p < 2; p++) {      // ni pairs (2p, 2p+1)
                uint32_t bq[4];
                int hoff = (wn + p * 16 + b_row) * LDH + ks * 16 + b_kh;
                ldm_x4(bq, sb + 2 * (SM_B + hoff));
#pragma unroll
                for (int mi = 0; mi < 2; mi++) {
                    mma_fp16(c[mi][2 * p + 0], a[mi], bq + 0);
                    mma_fp16(c[mi][2 * p + 1], a[mi], bq + 2);
                }
            }
        }
    }

    // --- epilogue: write fp16 H ---
    const int r0 = (lane >> 2);
    const int cb = (lane & 3) * 2;
#pragma unroll
    for (int mi = 0; mi < 2; mi++) {
#pragma unroll
        for (int ni = 0; ni < 4; ni++) {
            int col = wn + ni * 8 + cb;
            int gm0 = block_row + wm + mi * 16 + r0;
            int gm1 = gm0 + 8;
            if (gm0 < NN)
                *reinterpret_cast<__half2*>(g_Hh + (size_t)gm0 * OUTC + col) =
                    __floats2half2_rn(c[mi][ni][0], c[mi][ni][1]);
            if (gm1 < NN)
                *reinterpret_cast<__half2*>(g_Hh + (size_t)gm1 * OUTC + col) =
                    __floats2half2_rn(c[mi][ni][2], c[mi][ni][3]);
        }
    }
}

// ------------------------- Kernel 2: CSR row pointers (A_rows sorted) -------------------------
__global__ void row_ptr_kernel(const int* __restrict__ A_rows)
{
    int r = blockIdx.x * blockDim.x + threadIdx.x;
    if (r > NN) return;
    int lo = 0, hi = EE;
    while (lo < hi) {
        int mid = (lo + hi) >> 1;
        if (A_rows[mid] < r) lo = mid + 1;
        else                 hi = mid;
    }
    g_row_ptr[r] = lo;
}

// ------------------------- Kernel 3: CSR SpMM, warp per row (R11 + unroll 8) --------
__global__ __launch_bounds__(256)
void spmm_kernel(const int*   __restrict__ A_cols,
                 const float* __restrict__ A_vals,
                 float*       __restrict__ out)
{
    const int lane = threadIdx.x & 31;
    const int r    = blockIdx.x * 8 + (threadIdx.x >> 5);
    if (r >= NN) return;                       // warp-uniform

    const int beg = g_row_ptr[r];
    const int end = g_row_ptr[r + 1];

    float4 acc = make_float4(0.f, 0.f, 0.f, 0.f);
    const __half* __restrict__ Hbase = g_Hh;

#pragma unroll 1
    for (int base = beg; base < end; base += 32) {
        int   e   = base + lane;
        int   col = 0;
        float v   = 0.f;
        if (e < end) { col = __ldg(A_cols + e); v = __ldg(A_vals + e); }
        const int cnt = min(32, end - base);

#pragma unroll 8
        for (int j = 0; j < cnt; j++) {
            int   cj = __shfl_sync(0xffffffffu, col, j);
            float vj = __shfl_sync(0xffffffffu, v,   j);
            uint2 hraw = *reinterpret_cast<const uint2*>(
                             Hbase + (size_t)cj * OUTC + lane * 4);
            __half2 h0 = *reinterpret_cast<__half2*>(&hraw.x);
            __half2 h1 = *reinterpret_cast<__half2*>(&hraw.y);
            float2 f0 = __half22float2(h0);
            float2 f1 = __half22float2(h1);
            acc.x = fmaf(vj, f0.x, acc.x);
            acc.y = fmaf(vj, f0.y, acc.y);
            acc.z = fmaf(vj, f1.x, acc.z);
            acc.w = fmaf(vj, f1.y, acc.w);
        }
    }

    *reinterpret_cast<float4*>(out + (size_t)r * OUTC + lane * 4) = acc;
}

// ---------------------------------------------------------------------------
extern "C" void kernel_launch(void* const* d_in, const int* in_sizes, int n_in,
                              void* d_out, int out_size)
{
    const float* X      = (const float*)d_in[0];   // [NN, INC]
    const float* W      = (const float*)d_in[1];   // [OUTC, INC]
    const int*   A_rows = (const int*)  d_in[2];   // [EE] sorted
    const int*   A_cols = (const int*)  d_in[3];   // [EE]
    const float* A_vals = (const float*)d_in[4];   // [EE]
    float*       out    = (float*)d_out;           // [NN, OUTC]

    cudaFuncSetAttribute(gemm_tc_kernel,
                         cudaFuncAttributeMaxDynamicSharedMemorySize, SM_BYTES);

    wconv_kernel<<<(OUTC * INC + 255) / 256, 256>>>(W);
    gemm_tc_kernel<<<(NN + 127) / 128, 512, SM_BYTES>>>(X);
    row_ptr_kernel<<<(NN + 1 + 255) / 256, 256>>>(A_rows);
    spmm_kernel<<<(NN + 7) / 8, 256>>>(A_cols, A_vals, out);
}